// round 8
// baseline (speedup 1.0000x reference)
#include <cuda_runtime.h>
#include <math.h>

#define BB 64
#define NN 512
#define DD 128
#define MM 128
#define NEG_INF -1e9f

// Scratch (device globals)
__device__ float g_M[DD * DD];         // M[e][d] = Wk row e . Wq row d
__device__ float g_part[BB * 8 * 128]; // per-(batch,chunk) partial masked sums
__device__ int   g_ccnt[BB * 8];       // per-chunk active counts
__device__ float g_s[BB * NN];         // s_i = a_i^T M a_i (active rows only)
__device__ float g_G[BB * DD];         // per-batch G vector
__device__ float g_C[BB];              // per-batch scalar
__device__ int   g_arrive[BB];         // per-batch arrival counters (self-resetting)

__device__ __forceinline__ float warp_sum(float v) {
#pragma unroll
    for (int o = 16; o; o >>= 1) v += __shfl_xor_sync(0xffffffffu, v, o);
    return v;
}
__device__ __forceinline__ float warp_max(float v) {
#pragma unroll
    for (int o = 16; o; o >>= 1) v = fmaxf(v, __shfl_xor_sync(0xffffffffu, v, o));
    return v;
}
__device__ __forceinline__ float dot4(float4 a, float4 b) {
    return a.x * b.x + a.y * b.y + a.z * b.z + a.w * b.w;
}

// ---------------------------------------------------------------------------
// K0: M[e][d] = Wk row e . Wq row d   (16 blocks * 8 warps)
// ---------------------------------------------------------------------------
__global__ __launch_bounds__(256) void mcol_kernel(
    const float* __restrict__ Wq, const float* __restrict__ Wk)
{
    const int warp = threadIdx.x >> 5, lane = threadIdx.x & 31;
    const int e = blockIdx.x * 8 + warp;
    const float4* Wq4 = (const float4*)Wq;
    const float4* Wk4 = (const float4*)Wk;
    float4 wk = Wk4[e * 32 + lane];
    for (int d = 0; d < DD; d += 2) {
        float p0 = dot4(wk, Wq4[d * 32 + lane]);
        float p1 = dot4(wk, Wq4[(d + 1) * 32 + lane]);
        p0 = warp_sum(p0);
        p1 = warp_sum(p1);
        if (lane == 0) { g_M[e * DD + d] = p0; g_M[e * DD + d + 1] = p1; }
    }
}

// ---------------------------------------------------------------------------
// K1: grid 512 (8 chunks per batch), 256 threads. One smem staging of 64 rows
// serves: masked partial sums, chunk compaction, and s_i = a_i^T M a_i.
// Last block per batch computes stats (qs, C, G) inline.
// smem layout (bytes):
//   sM4   [4096 float4]  @0       65536
//   sA4   [2048 float4]  @65536   32768
//   sPart [8*128 float]  @98304    4096
//   asum  [128 float]    @102400    512
//   qs    [128 float]    @102912    512
//   sMask [64 float]     @103424    256
//   sLoc  [64 int]       @103680    256
//   sLast [int]          @103936      4
// ---------------------------------------------------------------------------
#define K1_SMEM 103944

__global__ __launch_bounds__(256) void quad_kernel(
    const float* __restrict__ A, const float* __restrict__ mask,
    const float* __restrict__ Wq, const float* __restrict__ Wk,
    const float* __restrict__ bq, const float* __restrict__ bk)
{
    extern __shared__ char smem[];
    float4* sM4   = (float4*)smem;
    float4* sA4   = (float4*)(smem + 65536);
    float*  sPart = (float*)(smem + 98304);
    float*  asum  = (float*)(smem + 102400);
    float*  qs    = (float*)(smem + 102912);
    float*  sMask = (float*)(smem + 103424);
    int*    sLoc  = (int*)(smem + 103680);
    int*    sLast = (int*)(smem + 103936);

    const int warp = threadIdx.x >> 5, lane = threadIdx.x & 31, tid = threadIdx.x;
    const int b = blockIdx.x >> 3;
    const int c = blockIdx.x & 7;
    const int r0 = c * 64;
    const size_t base = (size_t)b * NN;
    const float4* A4 = (const float4*)A;
    const float4* gM4 = (const float4*)g_M;
    const float4* Wq4 = (const float4*)Wq;
    const float4* Wk4 = (const float4*)Wk;

    // ---- stage M, A rows, mask; init sLoc ----
#pragma unroll 4
    for (int idx = tid; idx < 4096; idx += 256) sM4[idx] = gM4[idx];
#pragma unroll 2
    for (int idx = tid; idx < 2048; idx += 256) {
        int r = idx >> 5, col = idx & 31;
        sA4[idx] = A4[(base + r0 + r) * 32 + col];
    }
    if (tid < 64) { sMask[tid] = mask[base + r0 + tid]; sLoc[tid] = -1; }
    __syncthreads();

    // ---- masked partial sums (warp w -> rows w*8..w*8+7) ----
    {
        float4 acc = make_float4(0.f, 0.f, 0.f, 0.f);
#pragma unroll
        for (int j = 0; j < 8; j++) {
            int r = warp * 8 + j;
            float m = sMask[r];
            float4 a = sA4[r * 32 + lane];
            acc.x = fmaf(m, a.x, acc.x);
            acc.y = fmaf(m, a.y, acc.y);
            acc.z = fmaf(m, a.z, acc.z);
            acc.w = fmaf(m, a.w, acc.w);
        }
        ((float4*)(sPart + warp * 128))[lane] = acc;
    }

    // ---- chunk compaction (warp 0) ----
    if (warp == 0) {
        float m0 = sMask[lane];
        float m1 = sMask[32 + lane];
        unsigned b0 = __ballot_sync(0xffffffffu, m0 > 0.f);
        unsigned b1 = __ballot_sync(0xffffffffu, m1 > 0.f);
        int c0 = __popc(b0);
        int pre0 = __popc(b0 & ((1u << lane) - 1u));
        int pre1 = __popc(b1 & ((1u << lane) - 1u));
        if (m0 > 0.f) sLoc[pre0] = lane;
        if (m1 > 0.f) sLoc[c0 + pre1] = 32 + lane;
        if (lane == 0) g_ccnt[b * 8 + c] = c0 + __popc(b1);
    }
    __syncthreads();

    // ---- reduce partials to global ----
    if (tid < 128) {
        float s = 0.f;
#pragma unroll
        for (int w = 0; w < 8; w++) s += sPart[w * 128 + tid];
        g_part[((size_t)b * 8 + c) * 128 + tid] = s;
    }

    // ---- quadratic form on compacted rows (8 rows per warp) ----
    {
        const int rbase = warp * 8;
        float4 y[8];
#pragma unroll
        for (int r = 0; r < 8; r++) y[r] = make_float4(0.f, 0.f, 0.f, 0.f);

        int loc[8];
#pragma unroll
        for (int r = 0; r < 8; r++) loc[r] = sLoc[rbase + r];

        for (int e4 = 0; e4 < 32; e4++) {
            float4 av[8];
#pragma unroll
            for (int r = 0; r < 8; r++) {
                int l = (loc[r] >= 0) ? loc[r] : 0;
                av[r] = sA4[l * 32 + e4];
            }
#pragma unroll
            for (int s = 0; s < 4; s++) {
                float4 mc = sM4[(e4 * 4 + s) * 32 + lane];
#pragma unroll
                for (int r = 0; r < 8; r++) {
                    float a = (s == 0) ? av[r].x : (s == 1) ? av[r].y
                            : (s == 2) ? av[r].z : av[r].w;
                    y[r].x = fmaf(a, mc.x, y[r].x);
                    y[r].y = fmaf(a, mc.y, y[r].y);
                    y[r].z = fmaf(a, mc.z, y[r].z);
                    y[r].w = fmaf(a, mc.w, y[r].w);
                }
            }
        }
#pragma unroll
        for (int r = 0; r < 8; r++) {
            int l = (loc[r] >= 0) ? loc[r] : 0;
            float4 a = sA4[l * 32 + lane];
            float p = dot4(a, y[r]);
            p = warp_sum(p);
            if (lane == 0 && loc[r] >= 0) g_s[base + r0 + loc[r]] = p;
        }
    }

    // ---- last-block-done: per-batch stats ----
    __threadfence();
    __syncthreads();
    if (tid == 0) {
        int old = atomicAdd(&g_arrive[b], 1);
        *sLast = (old == 7) ? 1 : 0;
    }
    __syncthreads();
    if (*sLast) {
        int cnt = 0;
#pragma unroll
        for (int cc = 0; cc < 8; cc++) cnt += g_ccnt[b * 8 + cc];

        if (tid < 128) {
            float s = 0.f;
#pragma unroll
            for (int cc = 0; cc < 8; cc++) s += g_part[((size_t)b * 8 + cc) * 128 + tid];
            asum[tid] = s;
        }
        __syncthreads();

        if (tid < 128) {
            float q = (float)cnt * bq[tid];
#pragma unroll 8
            for (int d = 0; d < DD; d++) q = fmaf(asum[d], Wq[d * MM + tid], q);
            qs[tid] = q;
        }
        __syncthreads();

        if (warp == 0) {
            float cv = 0.f;
            for (int m = lane; m < MM; m += 32) cv = fmaf(bk[m], qs[m] - bq[m], cv);
            cv = warp_sum(cv);
            if (lane == 0) g_C[b] = cv;
        }

        {
            float4 qs4 = ((const float4*)qs)[lane];
            float4 bk4 = ((const float4*)bk)[lane];
#pragma unroll
            for (int d = warp; d < DD; d += 8) {
                float p = dot4(Wk4[d * 32 + lane], qs4) - dot4(Wq4[d * 32 + lane], bk4);
                p = warp_sum(p);
                if (lane == 0) g_G[b * DD + d] = p;
            }
        }
        if (tid == 0) atomicExch(&g_arrive[b], 0);   // reset for next replay
    }
}

// ---------------------------------------------------------------------------
// K2: per batch (1024 threads): agg = a.G - s + C (masked) -> normalize ->
//     softmax -> attn out; context = wsum@Wk + bk.
// ---------------------------------------------------------------------------
__global__ __launch_bounds__(1024) void softmax_ctx_kernel(
    const float* __restrict__ A, const float* __restrict__ mask,
    const float* __restrict__ Wk, const float* __restrict__ bk,
    float* __restrict__ out)
{
    const int b = blockIdx.x;
    const int warp = threadIdx.x >> 5, lane = threadIdx.x & 31, tid = threadIdx.x;
    const size_t base = (size_t)b * NN;
    const float4* A4 = (const float4*)A;

    __shared__ float sc[NN];
    __shared__ float sRed[32];
    __shared__ float sW[32][128];
    __shared__ float wsum[128];

    // pass 1: agg from linear term + precomputed quadratic term
    {
        float4 G4 = ((const float4*)(g_G + b * DD))[lane];
        const float C = g_C[b];
#pragma unroll
        for (int i = warp; i < NN; i += 32) {
            float m = mask[base + i];
            float4 a = A4[(base + i) * 32 + lane];
            float lin = dot4(a, G4);
            lin = warp_sum(lin);
            float s = g_s[base + i];
            if (lane == 0) sc[i] = (m > 0.f) ? (lin - s + C) : 0.f;
        }
    }
    __syncthreads();

    // sum of squares
    float ss = 0.f;
    for (int i = tid; i < NN; i += 1024) { float v = sc[i]; ss = fmaf(v, v, ss); }
    ss = warp_sum(ss);
    if (lane == 0) sRed[warp] = ss;
    __syncthreads();
    float tot = 0.f;
#pragma unroll
    for (int w = 0; w < 32; w++) tot += sRed[w];
    float inv = rsqrtf(tot);

    // scores + max
    float mx = -INFINITY;
    for (int i = tid; i < NN; i += 1024) {
        float m = mask[base + i];
        float s = (m > 0.f) ? sc[i] * inv : NEG_INF;
        sc[i] = s;
        mx = fmaxf(mx, s);
    }
    mx = warp_max(mx);
    __syncthreads();
    if (lane == 0) sRed[warp] = mx;
    __syncthreads();
    float M = -INFINITY;
#pragma unroll
    for (int w = 0; w < 32; w++) M = fmaxf(M, sRed[w]);

    // exp & sum
    float es = 0.f;
    for (int i = tid; i < NN; i += 1024) {
        float e = __expf(sc[i] - M);
        sc[i] = e;
        es += e;
    }
    es = warp_sum(es);
    __syncthreads();
    if (lane == 0) sRed[warp] = es;
    __syncthreads();
    float S = 0.f;
#pragma unroll
    for (int w = 0; w < 32; w++) S += sRed[w];
    float invS = 1.0f / S;

    // attn out
    for (int i = tid; i < NN; i += 1024) {
        float at = sc[i] * invS;
        sc[i] = at;
        out[base + i] = at;
    }
    __syncthreads();

    // wsum[d] = sum_i attn_i * A_i[d]
    float4 wacc = make_float4(0.f, 0.f, 0.f, 0.f);
#pragma unroll
    for (int i = warp; i < NN; i += 32) {
        float at = sc[i];
        float4 a = A4[(base + i) * 32 + lane];
        wacc.x = fmaf(at, a.x, wacc.x);
        wacc.y = fmaf(at, a.y, wacc.y);
        wacc.z = fmaf(at, a.z, wacc.z);
        wacc.w = fmaf(at, a.w, wacc.w);
    }
    ((float4*)sW[warp])[lane] = wacc;
    __syncthreads();
    if (tid < 128) {
        float s = 0.f;
#pragma unroll
        for (int w = 0; w < 32; w++) s += sW[w][tid];
        wsum[tid] = s;
    }
    __syncthreads();

    if (tid < 128) {
        float c = bk[tid];
#pragma unroll 8
        for (int d = 0; d < DD; d++) c = fmaf(wsum[d], Wk[d * MM + tid], c);
        out[(size_t)BB * NN + (size_t)b * MM + tid] = c;
    }
}

extern "C" void kernel_launch(void* const* d_in, const int* in_sizes, int n_in,
                              void* d_out, int out_size)
{
    const float* A    = (const float*)d_in[0];
    const float* mask = (const float*)d_in[1];
    const float* Wq   = (const float*)d_in[2];
    const float* bq   = (const float*)d_in[3];
    const float* Wk   = (const float*)d_in[4];
    const float* bk   = (const float*)d_in[5];
    float* out = (float*)d_out;

    cudaFuncSetAttribute(quad_kernel,
                         cudaFuncAttributeMaxDynamicSharedMemorySize, K1_SMEM);

    mcol_kernel<<<16, 256>>>(Wq, Wk);
    quad_kernel<<<BB * 8, 256, K1_SMEM>>>(A, mask, Wq, Wk, bq, bk);
    softmax_ctx_kernel<<<BB, 1024>>>(A, mask, Wk, bk, out);
}

// round 9
// speedup vs baseline: 1.2170x; 1.2170x over previous
#include <cuda_runtime.h>
#include <math.h>

#define BB 64
#define NN 512
#define DD 128
#define MM 128
#define NEG_INF -1e9f

// Scratch (device globals)
__device__ float g_M[DD * DD];         // M[e][d] = Wk row e . Wq row d
__device__ float g_part[BB * 8 * 128]; // per-(batch,chunk) partial masked sums
__device__ int   g_ccnt[BB * 8];       // per-chunk active counts
__device__ float g_s[BB * NN];         // s_i = a_i^T M a_i (active rows only)
__device__ float g_G[BB * DD];         // per-batch G vector
__device__ float g_C[BB];              // per-batch scalar
__device__ int   g_arrive[BB];         // per-batch arrival counters (self-resetting)

__device__ __forceinline__ float warp_sum(float v) {
#pragma unroll
    for (int o = 16; o; o >>= 1) v += __shfl_xor_sync(0xffffffffu, v, o);
    return v;
}
__device__ __forceinline__ float warp_max(float v) {
#pragma unroll
    for (int o = 16; o; o >>= 1) v = fmaxf(v, __shfl_xor_sync(0xffffffffu, v, o));
    return v;
}
__device__ __forceinline__ float dot4(float4 a, float4 b) {
    return a.x * b.x + a.y * b.y + a.z * b.z + a.w * b.w;
}

// ---------------------------------------------------------------------------
// K0: M[e][d] = Wk row e . Wq row d.
// Block per e (grid 128, 128 threads). Wk row e staged in smem; thread d does
// an unrolled float4 dot against Wq row d (32 independent loads -> high MLP).
// ---------------------------------------------------------------------------
__global__ __launch_bounds__(128) void mcol_kernel(
    const float* __restrict__ Wq, const float* __restrict__ Wk)
{
    __shared__ float4 wk[32];
    const int e = blockIdx.x;
    const int d = threadIdx.x;
    if (d < 32) wk[d] = ((const float4*)Wk)[e * 32 + d];
    __syncthreads();

    const float4* wq = (const float4*)(Wq + d * MM);
    float acc = 0.f;
#pragma unroll
    for (int m = 0; m < 32; m++) {
        float4 q = wq[m];
        float4 k = wk[m];
        acc = fmaf(q.x, k.x, acc);
        acc = fmaf(q.y, k.y, acc);
        acc = fmaf(q.z, k.z, acc);
        acc = fmaf(q.w, k.w, acc);
    }
    g_M[e * DD + d] = acc;
}

// ---------------------------------------------------------------------------
// K1: grid 512 (8 chunks per batch), 256 threads. One smem staging of 64 rows
// serves: masked partial sums, chunk compaction, and s_i = a_i^T M a_i
// (warps whose compacted row group is empty skip the mainloop).
// Last block per batch computes stats (qs, C, G) inline.
// ---------------------------------------------------------------------------
#define K1_SMEM 103944

__global__ __launch_bounds__(256) void quad_kernel(
    const float* __restrict__ A, const float* __restrict__ mask,
    const float* __restrict__ Wq, const float* __restrict__ Wk,
    const float* __restrict__ bq, const float* __restrict__ bk)
{
    extern __shared__ char smem[];
    float4* sM4   = (float4*)smem;                 // 65536
    float4* sA4   = (float4*)(smem + 65536);       // 32768
    float*  sPart = (float*)(smem + 98304);        //  4096
    float*  asum  = (float*)(smem + 102400);       //   512
    float*  qs    = (float*)(smem + 102912);       //   512
    float*  sMask = (float*)(smem + 103424);       //   256
    int*    sLoc  = (int*)(smem + 103680);         //   256
    int*    sLast = (int*)(smem + 103936);         //     4

    const int warp = threadIdx.x >> 5, lane = threadIdx.x & 31, tid = threadIdx.x;
    const int b = blockIdx.x >> 3;
    const int c = blockIdx.x & 7;
    const int r0 = c * 64;
    const size_t base = (size_t)b * NN;
    const float4* A4 = (const float4*)A;
    const float4* gM4 = (const float4*)g_M;
    const float4* Wq4 = (const float4*)Wq;
    const float4* Wk4 = (const float4*)Wk;

    // ---- stage M, A rows, mask; init sLoc ----
#pragma unroll 4
    for (int idx = tid; idx < 4096; idx += 256) sM4[idx] = gM4[idx];
#pragma unroll 2
    for (int idx = tid; idx < 2048; idx += 256) {
        int r = idx >> 5, col = idx & 31;
        sA4[idx] = A4[(base + r0 + r) * 32 + col];
    }
    if (tid < 64) { sMask[tid] = mask[base + r0 + tid]; sLoc[tid] = -1; }
    __syncthreads();

    // ---- masked partial sums (warp w -> rows w*8..w*8+7) ----
    {
        float4 acc = make_float4(0.f, 0.f, 0.f, 0.f);
#pragma unroll
        for (int j = 0; j < 8; j++) {
            int r = warp * 8 + j;
            float m = sMask[r];
            float4 a = sA4[r * 32 + lane];
            acc.x = fmaf(m, a.x, acc.x);
            acc.y = fmaf(m, a.y, acc.y);
            acc.z = fmaf(m, a.z, acc.z);
            acc.w = fmaf(m, a.w, acc.w);
        }
        ((float4*)(sPart + warp * 128))[lane] = acc;
    }

    // ---- chunk compaction (warp 0) ----
    if (warp == 0) {
        float m0 = sMask[lane];
        float m1 = sMask[32 + lane];
        unsigned b0 = __ballot_sync(0xffffffffu, m0 > 0.f);
        unsigned b1 = __ballot_sync(0xffffffffu, m1 > 0.f);
        int c0 = __popc(b0);
        int pre0 = __popc(b0 & ((1u << lane) - 1u));
        int pre1 = __popc(b1 & ((1u << lane) - 1u));
        if (m0 > 0.f) sLoc[pre0] = lane;
        if (m1 > 0.f) sLoc[c0 + pre1] = 32 + lane;
        if (lane == 0) g_ccnt[b * 8 + c] = c0 + __popc(b1);
    }
    __syncthreads();

    // ---- reduce partials to global ----
    if (tid < 128) {
        float s = 0.f;
#pragma unroll
        for (int w = 0; w < 8; w++) s += sPart[w * 128 + tid];
        g_part[((size_t)b * 8 + c) * 128 + tid] = s;
    }

    // ---- quadratic form on compacted rows; skip fully-empty warp groups ----
    {
        const int rbase = warp * 8;
        int loc[8];
#pragma unroll
        for (int r = 0; r < 8; r++) loc[r] = sLoc[rbase + r];

        if (loc[0] >= 0) {   // compacted: if slot 0 empty, all 8 are empty
            float4 y[8];
#pragma unroll
            for (int r = 0; r < 8; r++) y[r] = make_float4(0.f, 0.f, 0.f, 0.f);

            for (int e4 = 0; e4 < 32; e4++) {
                float4 av[8];
#pragma unroll
                for (int r = 0; r < 8; r++) {
                    int l = (loc[r] >= 0) ? loc[r] : 0;
                    av[r] = sA4[l * 32 + e4];
                }
#pragma unroll
                for (int s = 0; s < 4; s++) {
                    float4 mc = sM4[(e4 * 4 + s) * 32 + lane];
#pragma unroll
                    for (int r = 0; r < 8; r++) {
                        float a = (s == 0) ? av[r].x : (s == 1) ? av[r].y
                                : (s == 2) ? av[r].z : av[r].w;
                        y[r].x = fmaf(a, mc.x, y[r].x);
                        y[r].y = fmaf(a, mc.y, y[r].y);
                        y[r].z = fmaf(a, mc.z, y[r].z);
                        y[r].w = fmaf(a, mc.w, y[r].w);
                    }
                }
            }
#pragma unroll
            for (int r = 0; r < 8; r++) {
                int l = (loc[r] >= 0) ? loc[r] : 0;
                float4 a = sA4[l * 32 + lane];
                float p = dot4(a, y[r]);
                p = warp_sum(p);
                if (lane == 0 && loc[r] >= 0) g_s[base + r0 + loc[r]] = p;
            }
        }
    }

    // ---- last-block-done: per-batch stats ----
    __threadfence();
    __syncthreads();
    if (tid == 0) {
        int old = atomicAdd(&g_arrive[b], 1);
        *sLast = (old == 7) ? 1 : 0;
    }
    __syncthreads();
    if (*sLast) {
        int cnt = 0;
#pragma unroll
        for (int cc = 0; cc < 8; cc++) cnt += g_ccnt[b * 8 + cc];

        if (tid < 128) {
            float s = 0.f;
#pragma unroll
            for (int cc = 0; cc < 8; cc++) s += g_part[((size_t)b * 8 + cc) * 128 + tid];
            asum[tid] = s;
        }
        __syncthreads();

        if (tid < 128) {
            float q = (float)cnt * bq[tid];
#pragma unroll 8
            for (int d = 0; d < DD; d++) q = fmaf(asum[d], Wq[d * MM + tid], q);
            qs[tid] = q;
        }
        __syncthreads();

        if (warp == 0) {
            float cv = 0.f;
            for (int m = lane; m < MM; m += 32) cv = fmaf(bk[m], qs[m] - bq[m], cv);
            cv = warp_sum(cv);
            if (lane == 0) g_C[b] = cv;
        }

        {
            float4 qs4 = ((const float4*)qs)[lane];
            float4 bk4 = ((const float4*)bk)[lane];
#pragma unroll
            for (int d = warp; d < DD; d += 8) {
                float p = dot4(Wk4[d * 32 + lane], qs4) - dot4(Wq4[d * 32 + lane], bk4);
                p = warp_sum(p);
                if (lane == 0) g_G[b * DD + d] = p;
            }
        }
        if (tid == 0) atomicExch(&g_arrive[b], 0);   // reset for next replay
    }
}

// ---------------------------------------------------------------------------
// K2: per batch (1024 threads): agg = a.G - s + C (masked) -> normalize ->
//     softmax -> attn out; context = wsum@Wk + bk.
// ---------------------------------------------------------------------------
__global__ __launch_bounds__(1024) void softmax_ctx_kernel(
    const float* __restrict__ A, const float* __restrict__ mask,
    const float* __restrict__ Wk, const float* __restrict__ bk,
    float* __restrict__ out)
{
    const int b = blockIdx.x;
    const int warp = threadIdx.x >> 5, lane = threadIdx.x & 31, tid = threadIdx.x;
    const size_t base = (size_t)b * NN;
    const float4* A4 = (const float4*)A;

    __shared__ float sc[NN];
    __shared__ float sRed[32];
    __shared__ float sW[32][128];
    __shared__ float wsum[128];

    // pass 1: agg from linear term + precomputed quadratic term
    {
        float4 G4 = ((const float4*)(g_G + b * DD))[lane];
        const float C = g_C[b];
#pragma unroll
        for (int i = warp; i < NN; i += 32) {
            float m = mask[base + i];
            float4 a = A4[(base + i) * 32 + lane];
            float lin = dot4(a, G4);
            lin = warp_sum(lin);
            float s = g_s[base + i];
            if (lane == 0) sc[i] = (m > 0.f) ? (lin - s + C) : 0.f;
        }
    }
    __syncthreads();

    // sum of squares
    float ss = 0.f;
    for (int i = tid; i < NN; i += 1024) { float v = sc[i]; ss = fmaf(v, v, ss); }
    ss = warp_sum(ss);
    if (lane == 0) sRed[warp] = ss;
    __syncthreads();
    float tot = 0.f;
#pragma unroll
    for (int w = 0; w < 32; w++) tot += sRed[w];
    float inv = rsqrtf(tot);

    // scores + max
    float mx = -INFINITY;
    for (int i = tid; i < NN; i += 1024) {
        float m = mask[base + i];
        float s = (m > 0.f) ? sc[i] * inv : NEG_INF;
        sc[i] = s;
        mx = fmaxf(mx, s);
    }
    mx = warp_max(mx);
    __syncthreads();
    if (lane == 0) sRed[warp] = mx;
    __syncthreads();
    float M = -INFINITY;
#pragma unroll
    for (int w = 0; w < 32; w++) M = fmaxf(M, sRed[w]);

    // exp & sum
    float es = 0.f;
    for (int i = tid; i < NN; i += 1024) {
        float e = __expf(sc[i] - M);
        sc[i] = e;
        es += e;
    }
    es = warp_sum(es);
    __syncthreads();
    if (lane == 0) sRed[warp] = es;
    __syncthreads();
    float S = 0.f;
#pragma unroll
    for (int w = 0; w < 32; w++) S += sRed[w];
    float invS = 1.0f / S;

    // attn out
    for (int i = tid; i < NN; i += 1024) {
        float at = sc[i] * invS;
        sc[i] = at;
        out[base + i] = at;
    }
    __syncthreads();

    // wsum[d] = sum_i attn_i * A_i[d]
    float4 wacc = make_float4(0.f, 0.f, 0.f, 0.f);
#pragma unroll
    for (int i = warp; i < NN; i += 32) {
        float at = sc[i];
        float4 a = A4[(base + i) * 32 + lane];
        wacc.x = fmaf(at, a.x, wacc.x);
        wacc.y = fmaf(at, a.y, wacc.y);
        wacc.z = fmaf(at, a.z, wacc.z);
        wacc.w = fmaf(at, a.w, wacc.w);
    }
    ((float4*)sW[warp])[lane] = wacc;
    __syncthreads();
    if (tid < 128) {
        float s = 0.f;
#pragma unroll
        for (int w = 0; w < 32; w++) s += sW[w][tid];
        wsum[tid] = s;
    }
    __syncthreads();

    if (tid < 128) {
        float c = bk[tid];
#pragma unroll 8
        for (int d = 0; d < DD; d++) c = fmaf(wsum[d], Wk[d * MM + tid], c);
        out[(size_t)BB * NN + (size_t)b * MM + tid] = c;
    }
}

extern "C" void kernel_launch(void* const* d_in, const int* in_sizes, int n_in,
                              void* d_out, int out_size)
{
    const float* A    = (const float*)d_in[0];
    const float* mask = (const float*)d_in[1];
    const float* Wq   = (const float*)d_in[2];
    const float* bq   = (const float*)d_in[3];
    const float* Wk   = (const float*)d_in[4];
    const float* bk   = (const float*)d_in[5];
    float* out = (float*)d_out;

    cudaFuncSetAttribute(quad_kernel,
                         cudaFuncAttributeMaxDynamicSharedMemorySize, K1_SMEM);

    mcol_kernel<<<128, 128>>>(Wq, Wk);
    quad_kernel<<<BB * 8, 256, K1_SMEM>>>(A, mask, Wq, Wk, bq, bk);
    softmax_ctx_kernel<<<BB, 1024>>>(A, mask, Wk, bk, out);
}